// round 14
// baseline (speedup 1.0000x reference)
#include <cuda_runtime.h>

// B=2, C=8, 256x256 -> 1024x1024, CDF2.3 23-tap, two polyphase stages.
// Sparsity: odd taps all zero except w[11]; 12 even taps dense (values read
// from the real weight input each launch).
#define CH    8
#define NB    16
#define KTAPS 23

__device__ float g_s1[16ull * 512 * 512];   // stage-1 output (16MB)

typedef unsigned long long u64;
__device__ __forceinline__ u64 pack2(float lo, float hi) {
    u64 d; asm("mov.b64 %0, {%1, %2};" : "=l"(d) : "f"(lo), "f"(hi)); return d;
}
__device__ __forceinline__ u64 fma2(u64 a, u64 b, u64 c) {
    u64 d; asm("fma.rn.f32x2 %0, %1, %2, %3;" : "=l"(d) : "l"(a), "l"(b), "l"(c)); return d;
}
__device__ __forceinline__ u64 mul2(u64 a, u64 b) {
    u64 d; asm("mul.rn.f32x2 %0, %1, %2;" : "=l"(d) : "l"(a), "l"(b)); return d;
}
__device__ __forceinline__ u64 add2(u64 a, u64 b) {
    u64 d; asm("add.rn.f32x2 %0, %1, %2;" : "=l"(d) : "l"(a), "l"(b)); return d;
}

// ---------------------------------------------------------------------------
// Upsample stage: in (NB,H,W) -> out (NB,2H,2W), phase O.
// Out tile: RO rows x 256 cols; 256 threads; s_tmp[RO/2+11][256].
//  Phase H: j2 jobs (2 input cols -> 4 out cols = ONE quad). Window = 14
//   floats f[0..13] = input cols [cb, cb+14), cb = c0 + 2*jl - 6 (parity-
//   uniform float2 base). For out pair c = 2*jl + d (d=0,1):
//    O=0: out col 2c = f[6+d]*w11 ; 2c+1 = sum_t f[d+1+t]*we[t]
//    O=1: out col 2c = sum_t f[d+t]*we[t] ; 2c+1 = f[6+d]*w11
//   Store: one STS.128 at quad 4*jl -> lanes consecutive, conflict-free.
//  Phase V: thread = (col-pair p, half h); RO/2 rows per thread, rolling
//   12-row packed window; conv = sum win[t]wp[t], copy = win[5+O]w11.
//   O=0: row 2s = copy, 2s+1 = conv.  O=1: row 2s = conv, 2s+1 = copy.
// ---------------------------------------------------------------------------
template<int O, int H, int W, int RO>
__global__ void __launch_bounds__(256) fstage(const float* __restrict__ in,
                                              float* __restrict__ out,
                                              const float* __restrict__ wt)
{
    constexpr int NR = RO / 2 + 11;          // s_tmp rows
    __shared__ float s_tmp[NR][256];

    const int n = blockIdx.z;
    const float* wb = wt + (n & (CH - 1)) * KTAPS;
    float we[12];
#pragma unroll
    for (int t = 0; t < 12; t++) we[t] = __ldg(&wb[2 * t]);
    const float w11 = __ldg(&wb[11]);

    const int x0 = blockIdx.x * 256;         // output col base
    const int y0 = blockIdx.y * RO;          // output row base
    const int c0 = x0 >> 1;                  // input col base
    const int t0 = (y0 >> 1) - 5 - O;        // input row base (may be negative)
    const int tid = threadIdx.x;

    const float* __restrict__ ibase = in + (size_t)n * H * W;

    // ---- Phase H: NR rows x 64 j2 jobs ----
    for (int job = tid; job < NR * 64; job += 256) {
        const int rr = job >> 6, jl = job & 63;
        const int gr = (t0 + rr + H) & (H - 1);
        const float* __restrict__ row = ibase + (size_t)gr * W;
        const int cb = c0 + 2 * jl - 6;      // float2-aligned window base

        float f[14];
        if (cb >= 0 && cb + 14 <= W) {
#pragma unroll
            for (int q = 0; q < 7; q++) {
                float2 t2 = *(const float2*)(row + cb + 2 * q);
                f[2 * q] = t2.x; f[2 * q + 1] = t2.y;
            }
        } else {
#pragma unroll
            for (int q = 0; q < 14; q++)
                f[q] = row[(cb + q + W) & (W - 1)];
        }

        float o[4];
#pragma unroll
        for (int d = 0; d < 2; d++) {
            float a0 = 0.f, a1 = 0.f;        // split even/odd tap chains
            if (O == 1) {
#pragma unroll
                for (int t = 0; t < 12; t += 2) {
                    a0 = fmaf(f[d + t],     we[t],     a0);
                    a1 = fmaf(f[d + 1 + t], we[t + 1], a1);
                }
                o[2 * d]     = a0 + a1;
                o[2 * d + 1] = f[6 + d] * w11;
            } else {
#pragma unroll
                for (int t = 0; t < 12; t += 2) {
                    a0 = fmaf(f[d + 1 + t], we[t],     a0);
                    a1 = fmaf(f[d + 2 + t], we[t + 1], a1);
                }
                o[2 * d]     = f[6 + d] * w11;
                o[2 * d + 1] = a0 + a1;
            }
        }
        *(float4*)&s_tmp[rr][4 * jl] = make_float4(o[0], o[1], o[2], o[3]);
    }
    __syncthreads();

    // ---- Phase V: packed rolling-window vertical polyphase ----
    const int p = tid & 127;                 // cols 2p, 2p+1
    const int h = tid >> 7;                  // half: output rows (RO/2)*h ..
    constexpr int S = RO / 4;                // steps per half
    const int qb = S * h;                    // s_tmp row base

    u64 wp[12];
#pragma unroll
    for (int t = 0; t < 12; t++) wp[t] = pack2(we[t], we[t]);
    const u64 w11p = pack2(w11, w11);

    float* __restrict__ obase =
        out + ((size_t)n * 2 * H + y0 + (RO / 2) * h) * (2 * W) + x0 + 2 * p;

    u64 win[12];
#pragma unroll
    for (int q = 0; q < 12; q++)
        win[q] = *(const u64*)&s_tmp[qb + q][2 * p];

#pragma unroll
    for (int s = 0; s < S; s++) {
        u64 c0a = mul2(win[0], wp[0]);
        u64 c1a = mul2(win[1], wp[1]);
#pragma unroll
        for (int t = 2; t < 12; t += 2) {
            c0a = fma2(win[t],     wp[t],     c0a);
            c1a = fma2(win[t + 1], wp[t + 1], c1a);
        }
        const u64 cv  = add2(c0a, c1a);
        const u64 cpv = mul2(win[5 + O], w11p);
        if (O == 0) {
            *(u64*)(obase + (size_t)(2 * s)     * (2 * W)) = cpv;
            *(u64*)(obase + (size_t)(2 * s + 1) * (2 * W)) = cv;
        } else {
            *(u64*)(obase + (size_t)(2 * s)     * (2 * W)) = cv;
            *(u64*)(obase + (size_t)(2 * s + 1) * (2 * W)) = cpv;
        }
        if (s < S - 1) {
#pragma unroll
            for (int q = 0; q < 11; q++) win[q] = win[q + 1];
            win[11] = *(const u64*)&s_tmp[qb + s + 12][2 * p];
        }
    }
}

extern "C" void kernel_launch(void* const* d_in, const int* in_sizes, int n_in,
                              void* d_out, int out_size)
{
    (void)in_sizes; (void)n_in; (void)out_size;
    const float* img = (const float*)d_in[0];   // (2,8,256,256)
    const float* wt  = (const float*)d_in[1];   // (8,23)
    float* out = (float*)d_out;                 // (2,8,1024,1024)

    float* s1;
    cudaGetSymbolAddress((void**)&s1, g_s1);

    // Stage 1 (O=1): 256x256 -> 512x512; 32x256 tiles -> grid (2,16,16).
    fstage<1, 256, 256, 32><<<dim3(2, 16, NB), 256>>>(img, s1, wt);

    // Stage 2 (O=0): 512x512 -> 1024x1024; 64x256 tiles -> grid (4,16,16).
    fstage<0, 512, 512, 64><<<dim3(4, 16, NB), 256>>>(s1, out, wt);
}

// round 16
// speedup vs baseline: 1.0563x; 1.0563x over previous
#include <cuda_runtime.h>

// B=2, C=8, 256x256 -> 1024x1024, CDF2.3 23-tap, two polyphase stages.
// Sparsity: odd taps all zero except w[11]; 12 even taps dense (values read
// from the real weight input each launch).
#define CH    8
#define NB    16
#define KTAPS 23

__device__ float g_s1[16ull * 512 * 512];   // stage-1 output (16MB)

typedef unsigned long long u64;
__device__ __forceinline__ u64 pack2(float lo, float hi) {
    u64 d; asm("mov.b64 %0, {%1, %2};" : "=l"(d) : "f"(lo), "f"(hi)); return d;
}
__device__ __forceinline__ u64 fma2(u64 a, u64 b, u64 c) {
    u64 d; asm("fma.rn.f32x2 %0, %1, %2, %3;" : "=l"(d) : "l"(a), "l"(b), "l"(c)); return d;
}
__device__ __forceinline__ u64 mul2(u64 a, u64 b) {
    u64 d; asm("mul.rn.f32x2 %0, %1, %2;" : "=l"(d) : "l"(a), "l"(b)); return d;
}

// ---------------------------------------------------------------------------
// Upsample stage: in (NB,H,W) -> out (NB,2H,2W), phase O.
// Out tile: RO rows x 256 cols; 256 threads; s_tmp[RO/2+11][256].
//  Phase H (R10 form): 4-input-col jobs, 20-float window direct from global:
//   O=1: out col 2c = sum_t v[i+2+t]we[t], col 2c+1 = v[i+8]w11
//   O=0: out col 2c = v[i+8]w11,           col 2c+1 = sum_t v[i+3+t]we[t]
//  Phase V: thread = (col-pair p, half h); modular circular window of 12
//   packed rows, full unroll (indices compile-time, no register shifts).
//   Step s: conv rows qb+s..qb+s+11 -> win[(s+t)%12]; copy = win[(s+5+O)%12].
//   O=0: out row 2s = copy, 2s+1 = conv.  O=1: 2s = conv, 2s+1 = copy.
// ---------------------------------------------------------------------------
template<int O, int H, int W, int RO>
__global__ void __launch_bounds__(256) fstage(const float* __restrict__ in,
                                              float* __restrict__ out,
                                              const float* __restrict__ wt)
{
    constexpr int NR = RO / 2 + 11;          // s_tmp rows
    __shared__ float s_tmp[NR][256];

    const int n = blockIdx.z;
    const float* wb = wt + (n & (CH - 1)) * KTAPS;
    float we[12];
#pragma unroll
    for (int t = 0; t < 12; t++) we[t] = __ldg(&wb[2 * t]);
    const float w11 = __ldg(&wb[11]);

    const int x0 = blockIdx.x * 256;         // output col base
    const int y0 = blockIdx.y * RO;          // output row base
    const int c0 = x0 >> 1;                  // input col base
    const int t0 = (y0 >> 1) - 5 - O;        // input row base (may be negative)
    const int tid = threadIdx.x;

    const float* __restrict__ ibase = in + (size_t)n * H * W;

    // ---- Phase H: NR rows x 32 four-col jobs, direct from global ----
    for (int g = tid; g < NR * 32; g += 256) {
        const int rr = g >> 5, lc0 = (g & 31) << 2;
        const int gr = (t0 + rr + H) & (H - 1);
        const float* __restrict__ row = ibase + (size_t)gr * W;
        const int cb = c0 - 8 + lc0;         // window = input cols [cb, cb+19]

        float v[20];
        if (cb >= 0 && cb + 20 <= W) {       // cb % 4 == 0 by construction
#pragma unroll
            for (int q = 0; q < 5; q++) {
                float4 f = *(const float4*)(row + cb + 4 * q);
                v[4*q] = f.x; v[4*q+1] = f.y; v[4*q+2] = f.z; v[4*q+3] = f.w;
            }
        } else {
#pragma unroll
            for (int q = 0; q < 20; q++)
                v[q] = row[(cb + q + W) & (W - 1)];
        }

        float o8[8];
#pragma unroll
        for (int i = 0; i < 4; i++) {
            float cv = 0.f;
            if (O == 1) {
#pragma unroll
                for (int t = 0; t < 12; t++) cv = fmaf(v[i + 2 + t], we[t], cv);
                o8[2*i]   = cv;
                o8[2*i+1] = v[i + 8] * w11;
            } else {
#pragma unroll
                for (int t = 0; t < 12; t++) cv = fmaf(v[i + 3 + t], we[t], cv);
                o8[2*i]   = v[i + 8] * w11;
                o8[2*i+1] = cv;
            }
        }
        *(float4*)&s_tmp[rr][2 * lc0]     = make_float4(o8[0], o8[1], o8[2], o8[3]);
        *(float4*)&s_tmp[rr][2 * lc0 + 4] = make_float4(o8[4], o8[5], o8[6], o8[7]);
    }
    __syncthreads();

    // ---- Phase V: modular circular-window vertical polyphase ----
    const int p = tid & 127;                 // cols 2p, 2p+1
    const int h = tid >> 7;                  // half: output rows (RO/2)*h ..
    constexpr int S = RO / 4;                // steps per half
    const int qb = S * h;                    // s_tmp row base

    u64 wp[12];
#pragma unroll
    for (int t = 0; t < 12; t++) wp[t] = pack2(we[t], we[t]);
    const u64 w11p = pack2(w11, w11);

    float* __restrict__ obase =
        out + ((size_t)n * 2 * H + y0 + (RO / 2) * h) * (2 * W) + x0 + 2 * p;

    u64 win[12];
#pragma unroll
    for (int q = 0; q < 12; q++)
        win[q] = *(const u64*)&s_tmp[qb + q][2 * p];

#pragma unroll
    for (int s = 0; s < S; s++) {
        // conv over rows qb+s .. qb+s+11; win[(s+t)%12] holds row qb+s+t
        u64 cv = mul2(win[s % 12], wp[0]);
#pragma unroll
        for (int t = 1; t < 12; t++)
            cv = fma2(win[(s + t) % 12], wp[t], cv);
        const u64 cpv = mul2(win[(s + 5 + O) % 12], w11p);
        if (O == 0) {
            *(u64*)(obase + (size_t)(2 * s)     * (2 * W)) = cpv;
            *(u64*)(obase + (size_t)(2 * s + 1) * (2 * W)) = cv;
        } else {
            *(u64*)(obase + (size_t)(2 * s)     * (2 * W)) = cv;
            *(u64*)(obase + (size_t)(2 * s + 1) * (2 * W)) = cpv;
        }
        if (s < S - 1)                       // replace row qb+s with row qb+s+12
            win[s % 12] = *(const u64*)&s_tmp[qb + s + 12][2 * p];
    }
}

extern "C" void kernel_launch(void* const* d_in, const int* in_sizes, int n_in,
                              void* d_out, int out_size)
{
    (void)in_sizes; (void)n_in; (void)out_size;
    const float* img = (const float*)d_in[0];   // (2,8,256,256)
    const float* wt  = (const float*)d_in[1];   // (8,23)
    float* out = (float*)d_out;                 // (2,8,1024,1024)

    float* s1;
    cudaGetSymbolAddress((void**)&s1, g_s1);

    // Stage 1 (O=1): 256x256 -> 512x512; 32x256 tiles -> grid (2,16,16).
    fstage<1, 256, 256, 32><<<dim3(2, 16, NB), 256>>>(img, s1, wt);

    // Stage 2 (O=0): 512x512 -> 1024x1024; 64x256 tiles -> grid (4,16,16).
    fstage<0, 512, 512, 64><<<dim3(4, 16, NB), 256>>>(s1, out, wt);
}